// round 13
// baseline (speedup 1.0000x reference)
#include <cuda_runtime.h>
#include <cuda_fp16.h>
#include <cstdint>

// Shapes (fixed)
#define Bc   2
#define Sc   2048
#define Hc   32
#define KVHc 8
#define Dc   128
#define NUM_SLOTS 8192

#define BQ 64
#define BK 32
#define NTHREADS 128            // 4 warps; each warp owns 16 query rows
#define QTILES (Sc/BQ)          // 32
#define WCTAS  256              // fused KV-writer CTAs

#define OUT_ELEMS (Bc*Sc*Hc*Dc)
#define KV_ELEMS  (NUM_SLOTS*2*KVHc*Dc)
#define KN (Bc*Sc*KVHc*Dc)      // 4,194,304

// softmax scale * log2(e)  (applied to Q at staging)
#define SCALE2 ((float)(0.08838834764831845 * 1.4426950408889634))

// SMEM word (uint32) layout; row stride 68 words = 272B (272 mod 128 = 16 ->
// ldmatrix 8-row fetches hit distinct 16B chunks: conflict-free)
#define QKSTR 68
#define ROWB  (QKSTR*4)
#define SM_Qw 0                      // 64 rows: Q tile (17,408 B)
#define SM_S0 (64*QKSTR)             // stage 0: K(32) + V(32) rows (17,408 B)
#define SM_S1 (SM_S0 + 64*QKSTR)     // stage 1
#define STAGEB (64*QKSTR*4)          // 17,408 B per stage
#define SM_WORDS (SM_S1 + 64*QKSTR)  // 13,056 words = 52,224 B  -> 4 CTAs/SM

// fp16 scratch (pre-converted K/V) + inverse slot map
__device__ __half k16g[KN];
__device__ __half v16g[KN];
__device__ int inv_map[NUM_SLOTS];

__device__ __forceinline__ uint32_t h2(float a, float b) {
    __half2 h = __floats2half2_rn(a, b);
    return *(uint32_t*)&h;
}
__device__ __forceinline__ uint32_t exp2_pack(float lo, float hi) {
    uint32_t w;
    asm("cvt.rn.f16x2.f32 %0, %1, %2;" : "=r"(w) : "f"(hi), "f"(lo));
    asm("ex2.approx.f16x2 %0, %0;" : "+r"(w));
    return w;
}
__device__ __forceinline__ float ex2f(float x) {
    float r; asm("ex2.approx.f32 %0, %1;" : "=f"(r) : "f"(x)); return r;
}
__device__ __forceinline__ uint32_t smem_u32(const void* p) {
    uint32_t a;
    asm("{ .reg .u64 t; cvta.to.shared.u64 t, %1; cvt.u32.u64 %0, t; }" : "=r"(a) : "l"(p));
    return a;
}
__device__ __forceinline__ void cp16(uint32_t dst, const void* src) {
    asm volatile("cp.async.cg.shared.global [%0], [%1], 16;" :: "r"(dst), "l"(src));
}
#define CP_COMMIT() asm volatile("cp.async.commit_group;" ::: "memory")
#define CP_WAIT0()  asm volatile("cp.async.wait_group 0;" ::: "memory")

__device__ __forceinline__ void ldsm4(uint32_t* r, uint32_t addr) {
    asm volatile("ldmatrix.sync.aligned.m8n8.x4.shared.b16 {%0,%1,%2,%3}, [%4];"
                 : "=r"(r[0]), "=r"(r[1]), "=r"(r[2]), "=r"(r[3]) : "r"(addr));
}
__device__ __forceinline__ void ldsm4t(uint32_t* r, uint32_t addr) {
    asm volatile("ldmatrix.sync.aligned.m8n8.x4.trans.shared.b16 {%0,%1,%2,%3}, [%4];"
                 : "=r"(r[0]), "=r"(r[1]), "=r"(r[2]), "=r"(r[3]) : "r"(addr));
}
__device__ __forceinline__ void mma_f16(float* c, uint32_t a0, uint32_t a1, uint32_t a2,
                                        uint32_t a3, uint32_t b0, uint32_t b1) {
    asm volatile("mma.sync.aligned.m16n8k16.row.col.f32.f16.f16.f32 "
                 "{%0,%1,%2,%3}, {%4,%5,%6,%7}, {%8,%9}, {%0,%1,%2,%3};"
                 : "+f"(c[0]), "+f"(c[1]), "+f"(c[2]), "+f"(c[3])
                 : "r"(a0), "r"(a1), "r"(a2), "r"(a3), "r"(b0), "r"(b1));
}

// ---------------- prep: fp32 -> fp16 convert (K/V) + inv_map init ----------------
__global__ void convert_kernel(const float* __restrict__ xk, const float* __restrict__ xv) {
    int i = blockIdx.x * blockDim.x + threadIdx.x;
    if (i < NUM_SLOTS) inv_map[i] = -1;
    if (i < KN / 4) {
        float4 a = ((const float4*)xk)[i];
        *(uint2*)(k16g + 4 * (size_t)i) = make_uint2(h2(a.x, a.y), h2(a.z, a.w));
        float4 b = ((const float4*)xv)[i];
        *(uint2*)(v16g + 4 * (size_t)i) = make_uint2(h2(b.x, b.y), h2(b.z, b.w));
    }
}
__global__ void fill_inv_kernel(const int* __restrict__ sel) {
    int i = blockIdx.x * blockDim.x + threadIdx.x;
    if (i < Bc * Sc) inv_map[sel[i]] = i;
}

// ---------------- fused: fp16 flash attention + KV write-out ----------------
__global__ __launch_bounds__(NTHREADS, 4)
void attn_mma_kernel(const float* __restrict__ xq, const float* __restrict__ kvb,
                     const float* __restrict__ xk, const float* __restrict__ xv,
                     float* __restrict__ out, float* __restrict__ kv_out) {
    const int tid = threadIdx.x;

    // ---- KV-writer CTAs (no smem use, no syncs) ----
    if (blockIdx.x >= QTILES) {
        const int widx = (blockIdx.x - QTILES) + 4 * (blockIdx.y + 32 * blockIdx.z);
        const int per = KV_ELEMS / 4 / WCTAS;            // 16384 float4
        const size_t base = (size_t)widx * per;
        const int per_slot = 2 * KVHc * Dc / 4;          // 512
        const int per_tok  = KVHc * Dc / 4;              // 256
        for (int j = tid; j < per; j += NTHREADS) {
            size_t i = base + j;
            int slot = (int)(i / per_slot);
            int rem  = (int)(i - (size_t)slot * per_slot);
            int t = inv_map[slot];
            float4 v;
            if (t < 0)               v = ((const float4*)kvb)[i];
            else if (rem < per_tok)  v = ((const float4*)xk)[(size_t)t * per_tok + rem];
            else                     v = ((const float4*)xv)[(size_t)t * per_tok + rem - per_tok];
            ((float4*)kv_out)[i] = v;
        }
        return;
    }

    // ---- attention CTAs ----
    extern __shared__ uint32_t smw[];
    const uint32_t sb = smem_u32(smw);

    const int lane = tid & 31;
    const int warp = tid >> 5;     // 0..3
    const int g    = lane >> 2;
    const int c    = lane & 3;

    const int qt  = (QTILES - 1) - blockIdx.x;    // longest CTAs first
    const int h   = blockIdx.y;
    const int b   = blockIdx.z;
    const int kvh = h >> 2;
    const int q0  = qt * BQ;
    const int wr0 = q0 + warp * 16;               // warp's first query row

    const int qg0  = wr0 + g;
    const int qg1  = qg0 + 8;

    // ldmatrix per-lane base addresses (stage-0; add STAGEB for stage 1)
    const uint32_t qa  = sb + (uint32_t)(warp * 16 + (lane & 15)) * ROWB + ((lane >> 4) & 1) * 16;
    const uint32_t ka0 = sb + SM_S0 * 4
                       + (uint32_t)((lane & 7) + ((lane >> 4) & 1) * 8) * ROWB
                       + ((lane >> 3) & 1) * 16;
    const uint32_t va0 = sb + SM_S0 * 4 + 32 * ROWB
                       + (uint32_t)((lane & 7) + ((lane >> 3) & 1) * 8) * ROWB
                       + ((lane >> 4) & 1) * 16;

    const __half* kbase = k16g + ((size_t)(b * Sc) * KVHc + kvh) * Dc;
    const __half* vbase = v16g + ((size_t)(b * Sc) * KVHc + kvh) * Dc;
    const int niter = 2 * qt + 2;

    // staging: hoisted per-thread addressing (rows tid>>4 + 8k, chunk tid&15)
    const int sch = tid & 15, sr0 = tid >> 4;
    const uint32_t s_off = (uint32_t)sr0 * ROWB + sch * 16;
    const size_t  g_off = (size_t)sr0 * (KVHc * Dc) + sch * 8;

    // ---- prologue: convert+stage Q PRE-SCALED; cp.async stage 0 ----
    {
        const float* qb = xq + ((size_t)(b * Sc + q0) * Hc + h) * Dc;
        for (int idx = tid; idx < 64 * 32; idx += NTHREADS) {
            int c4 = idx & 31, row = idx >> 5;
            float4 v = *(const float4*)(qb + (size_t)row * (Hc * Dc) + c4 * 4);
            *(uint2*)(smw + SM_Qw + row * QKSTR + c4 * 2) =
                make_uint2(h2(v.x * SCALE2, v.y * SCALE2), h2(v.z * SCALE2, v.w * SCALE2));
        }
        const __half* kg = kbase + g_off;
        const __half* vg = vbase + g_off;
        uint32_t kd = sb + SM_S0 * 4 + s_off;
#pragma unroll
        for (int k = 0; k < 4; ++k) {
            cp16(kd + k * (8 * ROWB), kg + (size_t)k * (8 * KVHc * Dc));
            cp16(kd + 32 * ROWB + k * (8 * ROWB), vg + (size_t)k * (8 * KVHc * Dc));
        }
        CP_COMMIT();
    }

    float o[16][4];
#pragma unroll
    for (int n = 0; n < 16; ++n) { o[n][0] = o[n][1] = o[n][2] = o[n][3] = 0.0f; }
    float l0 = 0.0f, l1 = 0.0f;

    for (int it = 0; it < niter; ++it) {
        const int k0 = it * BK;

        CP_WAIT0();
        __syncthreads();

        if (it + 1 < niter) {
            const uint32_t sdst = sb + (((it + 1) & 1) ? SM_S1 : SM_S0) * 4 + s_off;
            const __half* kg = kbase + (size_t)(k0 + BK) * (KVHc * Dc) + g_off;
            const __half* vg = vbase + (size_t)(k0 + BK) * (KVHc * Dc) + g_off;
#pragma unroll
            for (int k = 0; k < 4; ++k) {
                cp16(sdst + k * (8 * ROWB), kg + (size_t)k * (8 * KVHc * Dc));
                cp16(sdst + 32 * ROWB + k * (8 * ROWB), vg + (size_t)k * (8 * KVHc * Dc));
            }
            CP_COMMIT();
        }

        if (k0 > wr0 + 15) continue;   // fully masked for this warp (warp-uniform)

        const uint32_t soff = (it & 1) ? (uint32_t)STAGEB : 0u;
        const uint32_t ka = ka0 + soff;
        const uint32_t va = va0 + soff;

        // ---- S = Q K^T : 8 ksteps x 4 ntiles ----
        float s[4][4];
#pragma unroll
        for (int n = 0; n < 4; ++n) { s[n][0] = s[n][1] = s[n][2] = s[n][3] = 0.0f; }
#pragma unroll
        for (int ks = 0; ks < 8; ++ks) {
            uint32_t a[4];
            ldsm4(a, qa + ks * 32);
#pragma unroll
            for (int j = 0; j < 2; ++j) {
                uint32_t kb[4];
                ldsm4(kb, ka + j * (16 * ROWB) + ks * 32);
                mma_f16(s[2 * j],     a[0], a[1], a[2], a[3], kb[0], kb[1]);
                mma_f16(s[2 * j + 1], a[0], a[1], a[2], a[3], kb[2], kb[3]);
            }
        }

        // ---- softmax: packed half2 exp2 -> A fragments; row sums on FMA pipe ----
        uint32_t pf[2][4];
        const bool domask = (k0 + 31 > wr0);   // warp-uniform
#pragma unroll
        for (int n = 0; n < 4; ++n) {
            float s0 = s[n][0], s1 = s[n][1], s2 = s[n][2], s3 = s[n][3];
            if (domask) {
                int kg = k0 + n * 8 + 2 * c;
                const float NINF = -__int_as_float(0x7f800000);
                if (kg + 0 > qg0) s0 = NINF;
                if (kg + 1 > qg0) s1 = NINF;
                if (kg + 0 > qg1) s2 = NINF;
                if (kg + 1 > qg1) s3 = NINF;
            }
            float p0 = ex2f(s0), p1 = ex2f(s1);
            float p2 = ex2f(s2), p3 = ex2f(s3);
            l0 += p0 + p1;
            l1 += p2 + p3;
            uint32_t w01 = h2(p0, p1);
            uint32_t w23 = h2(p2, p3);
            int ks = n >> 1;
            if (n & 1) { pf[ks][2] = w01; pf[ks][3] = w23; }
            else       { pf[ks][0] = w01; pf[ks][1] = w23; }
        }

        // ---- O += P V : 2 ksteps x 8 V fragments ----
#pragma unroll
        for (int ks = 0; ks < 2; ++ks) {
#pragma unroll
            for (int j = 0; j < 8; ++j) {
                uint32_t vb[4];
                ldsm4t(vb, va + ks * (16 * ROWB) + j * 32);
                mma_f16(o[2 * j],     pf[ks][0], pf[ks][1], pf[ks][2], pf[ks][3], vb[0], vb[1]);
                mma_f16(o[2 * j + 1], pf[ks][0], pf[ks][1], pf[ks][2], pf[ks][3], vb[2], vb[3]);
            }
        }
    }

    // ---- epilogue: quad row-sum reduce, normalize, store ----
    l0 += __shfl_xor_sync(0xffffffffu, l0, 1);
    l0 += __shfl_xor_sync(0xffffffffu, l0, 2);
    l1 += __shfl_xor_sync(0xffffffffu, l1, 1);
    l1 += __shfl_xor_sync(0xffffffffu, l1, 2);
    float inv0 = 1.0f / l0;
    float inv1 = 1.0f / l1;

    float* ob0 = out + ((size_t)(b * Sc + qg0) * Hc + h) * Dc;
    float* ob1 = out + ((size_t)(b * Sc + qg1) * Hc + h) * Dc;
#pragma unroll
    for (int n = 0; n < 16; ++n) {
        int col = n * 8 + 2 * c;
        *(float2*)(ob0 + col) = make_float2(o[n][0] * inv0, o[n][1] * inv0);
        *(float2*)(ob1 + col) = make_float2(o[n][2] * inv1, o[n][3] * inv1);
    }
}

// ---------------------------------------------------------------------------
extern "C" void kernel_launch(void* const* d_in, const int* in_sizes, int n_in,
                              void* d_out, int out_size) {
    const float* xq  = (const float*)d_in[0];
    const float* xk  = (const float*)d_in[1];
    const float* xv  = (const float*)d_in[2];
    const float* kvb = (const float*)d_in[3];
    const int*   sel = (const int*)d_in[4];

    float* out    = (float*)d_out;
    float* kv_out = out + OUT_ELEMS;

    // 1) convert K/V to fp16 + init inverse map
    convert_kernel<<<(KN / 4 + 255) / 256, 256>>>(xk, xv);
    // 2) fill inverse map
    fill_inv_kernel<<<(Bc * Sc + 255) / 256, 256>>>(sel);

    // 3) fused attention + KV write
    const int smem_bytes = SM_WORDS * 4;   // 52,224 B -> 4 CTAs/SM
    cudaFuncSetAttribute(attn_mma_kernel, cudaFuncAttributeMaxDynamicSharedMemorySize, smem_bytes);
    dim3 grid(QTILES + 4, Hc, Bc);   // (36, 32, 2): 2048 attn CTAs + 256 writer CTAs
    attn_mma_kernel<<<grid, NTHREADS, smem_bytes>>>(xq, kvb, xk, xv, out, kv_out);
}